// round 4
// baseline (speedup 1.0000x reference)
#include <cuda_runtime.h>

// CREStereo local correlation, fused warp(bilinear) + group correlation.
// left:  [B, C, H, W] f32
// right: [B, C, H, W] f32
// flow:  [B, 2, H, W] f32   (flow[:,0]=dx, flow[:,1]=dy)
// out:   [B, G*9, H, W] f32, out[b, g*9+o, y, x] =
//        mean_c( left[b, g*64+c, y, x] * warped[b, g*64+c, y, clamp(x+o-4)] )
// warped[b,c,y,x] = bilinear sample of right[b,c] at (x+dx, y+dy),
//                   zero outside [0,W-1]x[0,H-1] (align_corners-style abs coords).

#define BB   4
#define CC_T 256
#define HH   128
#define WW   256
#define GG   4
#define CG   64
#define WIN  9
#define PADW 4
#define CCH  8   // channels per shared chunk

__global__ __launch_bounds__(WW, 4)
void crestereo_corr_kernel(const float* __restrict__ left,
                           const float* __restrict__ right,
                           const float* __restrict__ flow,
                           float* __restrict__ out)
{
    __shared__ float sh[CCH][WW];

    // bid = ((b*H + y)*G + g): adjacent-y blocks launch adjacently -> L2 reuse
    // of gathered right rows across neighboring output rows.
    const int bid = blockIdx.x;
    const int g   = bid & (GG - 1);
    const int by  = bid >> 2;
    const int y   = by & (HH - 1);
    const int b   = by >> 7;

    const int x = threadIdx.x;

    // ---- per-pixel bilinear sampling parameters (computed once) ----
    const float fx = flow[((b * 2 + 0) * HH + y) * WW + x];
    const float fy = flow[((b * 2 + 1) * HH + y) * WW + x];
    const float sx = (float)x + fx;
    const float sy = (float)y + fy;
    const float x0f = floorf(sx);
    const float y0f = floorf(sy);
    const float axf = sx - x0f;
    const float ayf = sy - y0f;
    const int x0 = (int)x0f, y0 = (int)y0f;
    const int x1 = x0 + 1,   y1 = y0 + 1;

    float w00 = (1.f - axf) * (1.f - ayf);
    float w01 = axf * (1.f - ayf);
    float w10 = (1.f - axf) * ayf;
    float w11 = axf * ayf;

    const bool vx0 = ((unsigned)x0 < (unsigned)WW);
    const bool vx1 = ((unsigned)x1 < (unsigned)WW);
    const bool vy0 = ((unsigned)y0 < (unsigned)HH);
    const bool vy1 = ((unsigned)y1 < (unsigned)HH);
    if (!(vx0 && vy0)) w00 = 0.f;
    if (!(vx1 && vy0)) w01 = 0.f;
    if (!(vx0 && vy1)) w10 = 0.f;
    if (!(vx1 && vy1)) w11 = 0.f;

    const int cx0 = min(max(x0, 0), WW - 1);
    const int cx1 = min(max(x1, 0), WW - 1);
    const int cy0 = min(max(y0, 0), HH - 1);
    const int cy1 = min(max(y1, 0), HH - 1);
    const int o00 = cy0 * WW + cx0;
    const int o01 = cy0 * WW + cx1;
    const int o10 = cy1 * WW + cx0;
    const int o11 = cy1 * WW + cx1;

    const float* __restrict__ rbase = right + ((size_t)(b * CC_T + g * CG)) * (HH * WW);
    const float* __restrict__ lbase = left  + ((size_t)(b * CC_T + g * CG)) * (HH * WW)
                                            + (size_t)y * WW + x;

    // Replicate-pad correlation indices (constant per thread).
    int idxm[WIN];
#pragma unroll
    for (int o = 0; o < WIN; o++) idxm[o] = min(max(x + o - PADW, 0), WW - 1);

    float acc[WIN];
#pragma unroll
    for (int o = 0; o < WIN; o++) acc[o] = 0.f;

    for (int c0 = 0; c0 < CG; c0 += CCH) {
        float vreg[CCH];
        __syncthreads();   // previous chunk's reads complete before overwrite
#pragma unroll
        for (int cc = 0; cc < CCH; cc++) {
            const float* __restrict__ rp = rbase + (size_t)(c0 + cc) * (HH * WW);
            float v = w00 * __ldg(rp + o00) + w01 * __ldg(rp + o01)
                    + w10 * __ldg(rp + o10) + w11 * __ldg(rp + o11);
            vreg[cc]  = v;
            sh[cc][x] = v;
        }
        __syncthreads();
#pragma unroll
        for (int cc = 0; cc < CCH; cc++) {
            const float l = lbase[(size_t)(c0 + cc) * (HH * WW)];
#pragma unroll
            for (int o = 0; o < WIN; o++) {
                // center tap (o==PADW) is this thread's own value -> register
                const float wv = (o == PADW) ? vreg[cc] : sh[cc][idxm[o]];
                acc[o] = fmaf(l, wv, acc[o]);
            }
        }
    }

    const float scale = 1.f / (float)CG;
    float* __restrict__ ob = out + (((size_t)(b * GG + g) * WIN) * HH + y) * WW + x;
#pragma unroll
    for (int o = 0; o < WIN; o++)
        ob[(size_t)o * HH * WW] = acc[o] * scale;
}

extern "C" void kernel_launch(void* const* d_in, const int* in_sizes, int n_in,
                              void* d_out, int out_size)
{
    const float* left  = (const float*)d_in[0];
    const float* right = (const float*)d_in[1];
    const float* flow  = (const float*)d_in[2];
    float* out = (float*)d_out;

    const int grid = BB * HH * GG;   // 2048 CTAs, 256 threads each
    crestereo_corr_kernel<<<grid, WW>>>(left, right, flow, out);
}